// round 2
// baseline (speedup 1.0000x reference)
#include <cuda_runtime.h>
#include <math.h>

// Problem constants
#define Bn 32
#define Cn 8
#define Gn 2          // groups = C/4
#define HWn 65536     // 256*256
#define THRESH 0.7f

#define BLOCKS_PER_BG 32
#define NBG (Bn * Gn)                    // 64
#define NBLK (NBG * BLOCKS_PER_BG)       // 2048
#define THREADS 256
// pixels per block = HWn / BLOCKS_PER_BG = 2048 -> 512 float4 -> 2 iters of 256 threads

// Deterministic scratch: each block writes its own fixed slot. 4 floats per block:
// [bce_sum, msum, count, dnorm_sum]
__device__ float g_partial[NBLK * 4];

__global__ void __launch_bounds__(THREADS) lpmask_reduce1(
    const float* __restrict__ out, const float* __restrict__ tar)
{
    const int bgid = blockIdx.x / BLOCKS_PER_BG;   // 0..63  (b*2+g)
    const int blk  = blockIdx.x % BLOCKS_PER_BG;   // 0..31
    const int b = bgid >> 1;
    const int g = bgid & 1;

    const size_t base = (size_t)b * Cn * HWn + (size_t)g * 4 * HWn;
    const float4* __restrict__ o4 = (const float4*)(out + base);
    const float4* __restrict__ t4 = (const float4*)(tar + base);
    const int plane4 = HWn / 4;  // 16384 float4 per channel plane

    float bce  = 0.f;
    float msum = 0.f;
    float cnt  = 0.f;
    float dsum = 0.f;

    #pragma unroll
    for (int it = 0; it < 2; it++) {
        const int p4 = blk * 512 + it * 256 + threadIdx.x;

        float oc[4][4], tc[4][4];
        #pragma unroll
        for (int k = 0; k < 4; k++) {
            float4 v = o4[k * plane4 + p4];
            oc[k][0] = v.x; oc[k][1] = v.y; oc[k][2] = v.z; oc[k][3] = v.w;
            float4 w = t4[k * plane4 + p4];
            tc[k][0] = w.x; tc[k][1] = w.y; tc[k][2] = w.z; tc[k][3] = w.w;
        }

        #pragma unroll
        for (int j = 0; j < 4; j++) {
            // mask channel (channel 3 of the group)
            const float x  = oc[3][j];
            const float tm = tc[3][j];
            const float p  = 1.f / (1.f + expf(-x));
            // replicate reference: clip(log(p), -100), clip(log1p(-p), -100)
            const float logp   = fmaxf(logf(p), -100.f);
            const float log1mp = fmaxf(log1pf(-p), -100.f);
            bce += tm * logp + (1.f - tm) * log1mp;

            const float d0 = oc[0][j] - tc[0][j];
            const float d1 = oc[1][j] - tc[1][j];
            const float d2 = oc[2][j] - tc[2][j];
            const float dn = sqrtf(d0 * d0 + d1 * d1 + d2 * d2);
            dsum += dn;
            if (p > THRESH) {
                msum += dn;
                cnt  += (dn != 0.f) ? 1.f : 0.f;
            }
        }
    }

    // Block reduction: warp shuffles, then cross-warp via shared.
    #pragma unroll
    for (int off = 16; off > 0; off >>= 1) {
        bce  += __shfl_down_sync(0xffffffffu, bce,  off);
        msum += __shfl_down_sync(0xffffffffu, msum, off);
        cnt  += __shfl_down_sync(0xffffffffu, cnt,  off);
        dsum += __shfl_down_sync(0xffffffffu, dsum, off);
    }

    __shared__ float s[8][4];
    const int lane = threadIdx.x & 31;
    const int warp = threadIdx.x >> 5;
    if (lane == 0) {
        s[warp][0] = bce; s[warp][1] = msum; s[warp][2] = cnt; s[warp][3] = dsum;
    }
    __syncthreads();

    if (warp == 0 && lane < 8) {
        float v0 = s[lane][0], v1 = s[lane][1], v2 = s[lane][2], v3 = s[lane][3];
        #pragma unroll
        for (int off = 4; off > 0; off >>= 1) {
            v0 += __shfl_down_sync(0x000000ffu, v0, off);
            v1 += __shfl_down_sync(0x000000ffu, v1, off);
            v2 += __shfl_down_sync(0x000000ffu, v2, off);
            v3 += __shfl_down_sync(0x000000ffu, v3, off);
        }
        if (lane == 0) {
            float* dst = &g_partial[blockIdx.x * 4];
            dst[0] = v0; dst[1] = v1; dst[2] = v2; dst[3] = v3;
        }
    }
}

__global__ void lpmask_reduce2(float* __restrict__ out)
{
    // 1 block, 64 threads; thread i owns bg index i (b = i>>1, g = i&1)
    const int bg = threadIdx.x;

    float bce = 0.f, msum = 0.f, cnt = 0.f, dsum = 0.f;
    #pragma unroll 4
    for (int blk = 0; blk < BLOCKS_PER_BG; blk++) {
        const float* p = &g_partial[(bg * BLOCKS_PER_BG + blk) * 4];
        bce += p[0]; msum += p[1]; cnt += p[2]; dsum += p[3];
    }

    const float fallback   = dsum * (1.f / (float)HWn);
    const float per_sample = (cnt > 0.f) ? (msum / fmaxf(cnt, 1.f)) : fallback;

    __shared__ float sp[NBG], sb[NBG];
    sp[bg] = per_sample;
    sb[bg] = bce;
    __syncthreads();

    if (threadIdx.x == 0) {
        float loss = 0.f;
        for (int g = 0; g < Gn; g++) {
            float psum = 0.f, bsum = 0.f;
            for (int b = 0; b < Bn; b++) {
                psum += sp[b * Gn + g];
                bsum += sb[b * Gn + g];
            }
            const float mask_loss = -bsum / ((float)Bn * (float)HWn);
            const float nocs_loss = psum / (float)Bn;
            loss += 0.7f * mask_loss + 0.3f * nocs_loss;
        }
        out[0] = loss / (float)Gn;
    }
}

extern "C" void kernel_launch(void* const* d_in, const int* in_sizes, int n_in,
                              void* d_out, int out_size)
{
    const float* output = (const float*)d_in[0];
    const float* target = (const float*)d_in[1];
    float* out = (float*)d_out;

    lpmask_reduce1<<<NBLK, THREADS>>>(output, target);
    lpmask_reduce2<<<1, NBG>>>(out);
}